// round 9
// baseline (speedup 1.0000x reference)
#include <cuda_runtime.h>
#include <math.h>
#include <stddef.h>

// ---------------------------------------------------------------------------
// Problem constants
// ---------------------------------------------------------------------------
namespace {

constexpr int B  = 2048;
constexpr int N  = 64;
constexpr int D  = 512;
constexpr int H  = 8;
constexpr int HD = 64;
constexpr int L  = 3;
constexpr int FF = 2048;

constexpr size_t BND = (size_t)B * N * D;   // 67,108,864
constexpr size_t BD  = (size_t)B * D;       // 1,048,576
constexpr size_t BFF = (size_t)B * FF;      // 4,194,304
constexpr size_t WSZ = (size_t)L * D * D;   // 786,432

// scratch partition (one big device-global buffer)
constexpr size_t OFF_RG   = 0;               // r gathered      [B*N, D]
constexpr size_t OFF_EG   = OFF_RG  + BND;   // e gathered      [B*N, D]
constexpr size_t OFF_REW  = OFF_EG  + BND;   // r@W1 + e@W2     [B*N, D]
constexpr size_t OFF_VAL  = OFF_REW + BND;   // value           [B*N, D]
constexpr size_t OFF_KH   = OFF_VAL + BND;   // kh              [B*N, D]
constexpr size_t OFF_VH   = OFF_KH  + BND;   // vh              [B*N, D]
constexpr size_t OFF_H    = OFF_VH  + BND;   // h               [B, D]
constexpr size_t OFF_X    = OFF_H   + BD;    // residual branch [B, D]
constexpr size_t OFF_HW0  = OFF_X   + BD;    // h@W0 + msg_b    [B, D]
constexpr size_t OFF_QH   = OFF_HW0 + BD;    // qh              [B, D]
constexpr size_t OFF_EMBQ = OFF_QH  + BD;    // emb_q           [B, D]
constexpr size_t OFF_FF   = OFF_EMBQ+ BD;    // ff hidden       [B, FF]
constexpr size_t OFF_WQT  = OFF_FF  + BFF;   // Wq transposed   [L, D, D]
constexpr size_t OFF_WKT  = OFF_WQT + WSZ;
constexpr size_t OFF_WVT  = OFF_WKT + WSZ;
constexpr size_t TOTAL    = OFF_WVT + WSZ;   // 414,449,664 floats (~1.54 GiB)

__device__ float g_buf[TOTAL];

// ---------------------------------------------------------------------------
// Generic fp32 GEMM: C[M,Nc] = act( A[M,K] @ Bm[K,Nc] (+bias) (+C) )
// 128x128 block tile, BK=8, 256 threads, 8x8 per-thread register tile.
// Requires M%128==0, Nc%128==0, K%8==0 (true for all call sites here).
// ACT: 0=none, 1=relu, 2=leaky_relu(0.01)
// ---------------------------------------------------------------------------
template <int ACT, bool ACCUM, bool BIAS>
__global__ void __launch_bounds__(256) sgemm_k(
    const float* __restrict__ A, const float* __restrict__ Bm,
    const float* __restrict__ bias, float* __restrict__ C,
    int M, int Nc, int K)
{
    __shared__ float As[8][128];
    __shared__ float Bs[8][128];

    const int bm  = blockIdx.y * 128;
    const int bn  = blockIdx.x * 128;
    const int tid = threadIdx.x;
    const int tx  = tid & 15;        // 0..15 -> col group
    const int ty  = tid >> 4;        // 0..15 -> row group

    const int arow = tid >> 1;       // 0..127
    const int acol = (tid & 1) * 4;  // 0 or 4
    const int brow = tid >> 5;       // 0..7
    const int bcol = (tid & 31) * 4; // 0..124

    const float* Ap = A  + (size_t)(bm + arow) * K + acol;
    const float* Bp = Bm + (size_t)brow * Nc + bn + bcol;

    float acc[8][8];
#pragma unroll
    for (int i = 0; i < 8; i++)
#pragma unroll
        for (int j = 0; j < 8; j++) acc[i][j] = 0.0f;

    for (int k0 = 0; k0 < K; k0 += 8) {
        float4 av = *(const float4*)Ap;
        As[acol + 0][arow] = av.x;
        As[acol + 1][arow] = av.y;
        As[acol + 2][arow] = av.z;
        As[acol + 3][arow] = av.w;
        *(float4*)(&Bs[brow][bcol]) = *(const float4*)Bp;
        __syncthreads();

#pragma unroll
        for (int k = 0; k < 8; k++) {
            float ra[8], rb[8];
            *(float4*)(ra)     = *(const float4*)(&As[k][ty * 8]);
            *(float4*)(ra + 4) = *(const float4*)(&As[k][ty * 8 + 4]);
            *(float4*)(rb)     = *(const float4*)(&Bs[k][tx * 8]);
            *(float4*)(rb + 4) = *(const float4*)(&Bs[k][tx * 8 + 4]);
#pragma unroll
            for (int i = 0; i < 8; i++)
#pragma unroll
                for (int j = 0; j < 8; j++)
                    acc[i][j] = fmaf(ra[i], rb[j], acc[i][j]);
        }
        __syncthreads();
        Ap += 8;
        Bp += (size_t)8 * Nc;
    }

#pragma unroll
    for (int i = 0; i < 8; i++) {
        const size_t base = (size_t)(bm + ty * 8 + i) * Nc + bn + tx * 8;
        float vals[8];
#pragma unroll
        for (int j = 0; j < 8; j++) {
            float v = acc[i][j];
            if (BIAS)  v += bias[bn + tx * 8 + j];
            if (ACCUM) v += C[base + j];
            if (ACT == 1) v = fmaxf(v, 0.0f);
            else if (ACT == 2) v = (v > 0.0f) ? v : 0.01f * v;
            vals[j] = v;
        }
        *(float4*)(&C[base])     = *(float4*)(vals);
        *(float4*)(&C[base + 4]) = *(float4*)(vals + 4);
    }
}

// ---------------------------------------------------------------------------
// Row gather: dst[m, :] = table[idx[m], :]   (D floats per row, float4-wide)
// Launch with exactly M*D/4 threads.
// ---------------------------------------------------------------------------
__global__ void gather_rows_k(const float* __restrict__ table,
                              const int* __restrict__ idx,
                              float* __restrict__ dst, int M)
{
    size_t i = (size_t)blockIdx.x * blockDim.x + threadIdx.x;
    if (i >= (size_t)M * (D / 4)) return;
    int row = (int)(i >> 7);   // D/4 == 128
    int c   = (int)(i & 127);
    ((float4*)dst)[i] =
        ((const float4*)(table + (size_t)idx[row] * D))[c];
}

// ---------------------------------------------------------------------------
// Weight re-layout: [L,H,D,HD] -> [L, D, H*HD]  (so projections are plain GEMMs)
// ---------------------------------------------------------------------------
__global__ void transpose_w_k(const float* __restrict__ src, float* __restrict__ dst)
{
    int i = blockIdx.x * blockDim.x + threadIdx.x;
    if (i >= (int)WSZ) return;
    int l   = i / (D * D);
    int rem = i % (D * D);
    int d   = rem / D;
    int c   = rem % D;          // c = h*HD + e
    int h   = c / HD;
    int e   = c % HD;
    dst[i] = src[(((size_t)l * H + h) * D + d) * HD + e];
}

// ---------------------------------------------------------------------------
// value[b,n,:] = leaky_relu(hW0[b,:] + reW[b,n,:])   (float4-wide)
// Launch with exactly BND/4 threads.
// ---------------------------------------------------------------------------
__global__ void msg_combine_k(const float* __restrict__ hw0,
                              const float* __restrict__ reW,
                              float* __restrict__ val)
{
    size_t i = (size_t)blockIdx.x * blockDim.x + threadIdx.x;
    if (i >= BND / 4) return;
    size_t e = i * 4;
    int b = (int)(e / ((size_t)N * D));
    int d = (int)(e % D);
    float4 rv = ((const float4*)reW)[i];
    float4 hv = *(const float4*)(hw0 + (size_t)b * D + d);
    float4 o;
    float t;
    t = rv.x + hv.x; o.x = (t > 0.0f) ? t : 0.01f * t;
    t = rv.y + hv.y; o.y = (t > 0.0f) ? t : 0.01f * t;
    t = rv.z + hv.z; o.z = (t > 0.0f) ? t : 0.01f * t;
    t = rv.w + hv.w; o.w = (t > 0.0f) ? t : 0.01f * t;
    ((float4*)val)[i] = o;
}

// ---------------------------------------------------------------------------
// Fused masked attention for one (b, h): scores -> softmax -> weighted sum.
// 64 threads per block; grid = B*H. Shared tiles padded (stride 65) so the
// score dot-product reads are bank-conflict-free.
// ---------------------------------------------------------------------------
__global__ void attn_k(const float* __restrict__ qh, const float* __restrict__ kh,
                       const float* __restrict__ vh, const float* __restrict__ masks,
                       float* __restrict__ xout)
{
    const int b = blockIdx.x >> 3;
    const int h = blockIdx.x & 7;
    const int t = threadIdx.x;            // 0..63
    const int hbase = h * HD;

    __shared__ float tile[64][65];
    __shared__ float qs[64];
    __shared__ float red[64];
    __shared__ float at[64];

    qs[t] = qh[(size_t)b * D + hbase + t];

    const float* kb = kh + (size_t)b * N * D + hbase;
    for (int i = t; i < N * HD; i += 64)
        tile[i >> 6][i & 63] = kb[(size_t)(i >> 6) * D + (i & 63)];
    __syncthreads();

    // score for neighbor n = t
    float s = 0.0f;
#pragma unroll 8
    for (int d = 0; d < HD; d++) s = fmaf(qs[d], tile[t][d], s);
    s = s * 0.125f - 1e31f * (1.0f - masks[b * N + t]);

    // max-reduce
    red[t] = s; __syncthreads();
    for (int off = 32; off; off >>= 1) {
        if (t < off) red[t] = fmaxf(red[t], red[t + off]);
        __syncthreads();
    }
    const float mx = red[0];
    __syncthreads();

    // sum-reduce of exp
    const float ex = expf(s - mx);
    red[t] = ex; __syncthreads();
    for (int off = 32; off; off >>= 1) {
        if (t < off) red[t] += red[t + off];
        __syncthreads();
    }
    at[t] = ex / red[0];
    __syncthreads();

    // weighted sum of vh (reuse tile)
    const float* vb = vh + (size_t)b * N * D + hbase;
    for (int i = t; i < N * HD; i += 64)
        tile[i >> 6][i & 63] = vb[(size_t)(i >> 6) * D + (i & 63)];
    __syncthreads();

    float o = 0.0f;
#pragma unroll 8
    for (int n = 0; n < N; n++) o = fmaf(at[n], tile[n][t], o);
    xout[(size_t)b * D + hbase + t] = o;
}

// ---------------------------------------------------------------------------
// hout[b,:] = layernorm(hin[b,:] + xin[b,:]) * g + beta   (biased var, eps 1e-5)
// 128 threads per block (4 elems each), grid = B. In-place safe (hout==hin).
// ---------------------------------------------------------------------------
__global__ void ln_res_k(const float* __restrict__ hin, const float* __restrict__ xin,
                         const float* __restrict__ g, const float* __restrict__ beta,
                         float* __restrict__ hout)
{
    const int b = blockIdx.x;
    const int t = threadIdx.x;  // 0..127
    float v[4];
    float s = 0.0f, s2 = 0.0f;
#pragma unroll
    for (int i = 0; i < 4; i++) {
        int d = t + i * 128;
        float y = hin[(size_t)b * D + d] + xin[(size_t)b * D + d];
        v[i] = y; s += y; s2 += y * y;
    }
    for (int off = 16; off; off >>= 1) {
        s  += __shfl_down_sync(0xffffffffu, s,  off);
        s2 += __shfl_down_sync(0xffffffffu, s2, off);
    }
    __shared__ float ss[4], ss2[4];
    const int w = t >> 5, lane = t & 31;
    if (lane == 0) { ss[w] = s; ss2[w] = s2; }
    __syncthreads();
    if (t == 0) {
        ss[0]  = ss[0] + ss[1] + ss[2] + ss[3];
        ss2[0] = ss2[0] + ss2[1] + ss2[2] + ss2[3];
    }
    __syncthreads();
    const float mean = ss[0] * (1.0f / D);
    const float var  = ss2[0] * (1.0f / D) - mean * mean;
    const float rstd = rsqrtf(var + 1e-5f);
#pragma unroll
    for (int i = 0; i < 4; i++) {
        int d = t + i * 128;
        hout[(size_t)b * D + d] = (v[i] - mean) * rstd * g[d] + beta[d];
    }
}

} // anonymous namespace

// ---------------------------------------------------------------------------
// Host orchestration (graph-capturable: kernel launches + D2D memcpyAsync only)
// ---------------------------------------------------------------------------
extern "C" void kernel_launch(void* const* d_in, const int* in_sizes, int n_in,
                              void* d_out, int out_size)
{
    const int*   e1_idx = (const int*)  d_in[0];
    const int*   q_idx  = (const int*)  d_in[1];
    const int*   nbr_r  = (const int*)  d_in[2];
    const int*   nbr_e  = (const int*)  d_in[3];
    const float* masks  = (const float*)d_in[4];
    const float* emb_e  = (const float*)d_in[5];
    const float* emb_r  = (const float*)d_in[6];
    const float* msg_W  = (const float*)d_in[7];
    const float* msg_b  = (const float*)d_in[8];
    const float* Wq     = (const float*)d_in[9];
    const float* bq     = (const float*)d_in[10];
    const float* Wk     = (const float*)d_in[11];
    const float* bk     = (const float*)d_in[12];
    const float* Wv     = (const float*)d_in[13];
    const float* bv     = (const float*)d_in[14];
    const float* ffW1   = (const float*)d_in[15];
    const float* ffb1   = (const float*)d_in[16];
    const float* ffW2   = (const float*)d_in[17];
    const float* ffb2   = (const float*)d_in[18];
    const float* ln1g   = (const float*)d_in[19];
    const float* ln1b   = (const float*)d_in[20];
    const float* ln2g   = (const float*)d_in[21];
    const float* ln2b   = (const float*)d_in[22];
    float*       out    = (float*)d_out;

    float* buf = nullptr;
    cudaGetSymbolAddress((void**)&buf, g_buf);

    float* rg   = buf + OFF_RG;
    float* eg   = buf + OFF_EG;
    float* reW  = buf + OFF_REW;
    float* val  = buf + OFF_VAL;
    float* khb  = buf + OFF_KH;
    float* vhb  = buf + OFF_VH;
    float* hb   = buf + OFF_H;
    float* xb   = buf + OFF_X;
    float* hw0  = buf + OFF_HW0;
    float* qhb  = buf + OFF_QH;
    float* embq = buf + OFF_EMBQ;
    float* ffm  = buf + OFF_FF;
    float* wqt  = buf + OFF_WQT;
    float* wkt  = buf + OFF_WKT;
    float* wvt  = buf + OFF_WVT;

    const int BN = B * N;

    // --- weight re-layout (tiny) ---
    const int TGRID = (int)((WSZ + 255) / 256);
    transpose_w_k<<<TGRID, 256>>>(Wq, wqt);
    transpose_w_k<<<TGRID, 256>>>(Wk, wkt);
    transpose_w_k<<<TGRID, 256>>>(Wv, wvt);

    // --- gathers ---
    gather_rows_k<<<(int)(BN * (D / 4) / 256), 256>>>(emb_r, nbr_r, rg, BN);
    gather_rows_k<<<(int)(BN * (D / 4) / 256), 256>>>(emb_e, nbr_e, eg, BN);
    gather_rows_k<<<(int)(B  * (D / 4) / 256), 256>>>(emb_e, e1_idx, hb, B);
    gather_rows_k<<<(int)(B  * (D / 4) / 256), 256>>>(emb_r, q_idx, embq, B);

    const dim3 gBig(D / 128, BN / 128);   // (4, 1024)
    const dim3 gSm(D / 128, B / 128);     // (4, 16)
    const dim3 gFF1(FF / 128, B / 128);   // (16, 16)
    const int  CMB = (int)(BND / 4 / 256);

    // --- layer-invariant neighbor term: reW = r@W1 + e@W2 ---
    sgemm_k<0, false, false><<<gBig, 256>>>(rg, msg_W + (size_t)D * D,     nullptr, reW, BN, D, D);
    sgemm_k<0, true,  false><<<gBig, 256>>>(eg, msg_W + (size_t)2 * D * D, nullptr, reW, BN, D, D);

    // --- initial value = leaky_relu(h@W0 + msg_b + reW) ---
    sgemm_k<0, false, true><<<gSm, 256>>>(hb, msg_W, msg_b, hw0, B, D, D);
    msg_combine_k<<<CMB, 256>>>(hw0, reW, val);

    for (int l = 0; l < L; l++) {
        // projections
        sgemm_k<0, false, true><<<gSm,  256>>>(embq, wqt + (size_t)l * D * D, bq + l * D, qhb, B,  D, D);
        sgemm_k<0, false, true><<<gBig, 256>>>(rg,   wkt + (size_t)l * D * D, bk + l * D, khb, BN, D, D);
        sgemm_k<0, false, true><<<gBig, 256>>>(val,  wvt + (size_t)l * D * D, bv + l * D, vhb, BN, D, D);

        // masked attention
        attn_k<<<B * H, 64>>>(qhb, khb, vhb, masks, xb);

        // h = LN1(h + attn)
        ln_res_k<<<B, 128>>>(hb, xb, ln1g + l * D, ln1b + l * D, hb);

        // FF
        sgemm_k<1, false, true><<<gFF1, 256>>>(hb,  ffW1 + (size_t)l * D * FF, ffb1 + l * FF, ffm, B, FF, D);
        sgemm_k<0, false, true><<<gSm,  256>>>(ffm, ffW2 + (size_t)l * FF * D, ffb2 + l * D,  xb,  B, D, FF);

        // h = LN2(h + ff)
        ln_res_k<<<B, 128>>>(hb, xb, ln2g + l * D, ln2b + l * D, hb);

        // value for next layer (skip after last layer — dead in reference)
        if (l + 1 < L) {
            sgemm_k<0, false, true><<<gSm, 256>>>(hb, msg_W, msg_b, hw0, B, D, D);
            msg_combine_k<<<CMB, 256>>>(hw0, reW, val);
        }
    }

    // output = concat(h [B,D], emb_q [B,D])
    cudaMemcpyAsync(out, hb, BD * sizeof(float), cudaMemcpyDeviceToDevice);
    if ((size_t)out_size >= 2 * BD)
        cudaMemcpyAsync(out + BD, embq, BD * sizeof(float), cudaMemcpyDeviceToDevice);
}

// round 10
// speedup vs baseline: 3.4687x; 3.4687x over previous
#include <cuda_runtime.h>
#include <math.h>
#include <stddef.h>

namespace {

constexpr int B  = 2048;
constexpr int N  = 64;
constexpr int D  = 512;
constexpr int H  = 8;
constexpr int HD = 64;
constexpr int L  = 3;
constexpr int FF = 2048;
constexpr int E_ = 100000;
constexpr int R_ = 400;

constexpr size_t BD  = (size_t)B * D;
constexpr size_t BFF = (size_t)B * FF;
constexpr size_t WSZ = (size_t)L * D * D;
constexpr size_t EPAD = 100096;              // 782 * 128

constexpr size_t OFF_ETAB = 0;                         // emb_e @ W2        [E, D]
constexpr size_t OFF_RTAB = OFF_ETAB + EPAD * D;       // emb_r @ W1        [512, D]
constexpr size_t OFF_QTAB = OFF_RTAB + (size_t)512 * D;
constexpr size_t OFF_KTAB = OFF_QTAB + (size_t)512 * D;
constexpr size_t OFF_ATTN = OFF_KTAB + (size_t)512 * D;   // attn weights [B,H,N]
constexpr size_t OFF_VSUM = OFF_ATTN + (size_t)B * H * N; // vsum [H,B,D]
constexpr size_t OFF_H    = OFF_VSUM + (size_t)H * B * D;
constexpr size_t OFF_X    = OFF_H    + BD;
constexpr size_t OFF_HW0  = OFF_X    + BD;
constexpr size_t OFF_EMBQ = OFF_HW0  + BD;
constexpr size_t OFF_FFM  = OFF_EMBQ + BD;
constexpr size_t OFF_WQT  = OFF_FFM  + BFF;
constexpr size_t OFF_WKT  = OFF_WQT  + WSZ;
constexpr size_t OFF_WVT  = OFF_WKT  + WSZ;
constexpr size_t TOTAL    = OFF_WVT  + WSZ;   // ~75M floats (~300 MB)

__device__ float g_buf[TOTAL];

// ---------------------------------------------------------------------------
// fp32 GEMM: C[M,Nc] = act( A[M,K] @ Bm[K,Nc] (+bias) ), 128x128 tile, BK=8,
// 256 threads, 8x8 per-thread. Nc%128==0, K%8==0 always. MGUARD handles
// arbitrary M (clamped loads, guarded stores).  ACT: 0=none, 1=relu.
// ---------------------------------------------------------------------------
template <int ACT, bool BIAS, bool MGUARD>
__global__ void __launch_bounds__(256) sgemm_k(
    const float* __restrict__ A, const float* __restrict__ Bm,
    const float* __restrict__ bias, float* __restrict__ C,
    int M, int Nc, int K)
{
    __shared__ float As[8][128];
    __shared__ float Bs[8][128];

    const int bm  = blockIdx.y * 128;
    const int bn  = blockIdx.x * 128;
    const int tid = threadIdx.x;
    const int tx  = tid & 15;
    const int ty  = tid >> 4;

    int arow = bm + (tid >> 1);
    if (MGUARD && arow >= M) arow = M - 1;
    const int acol = (tid & 1) * 4;
    const int brow = tid >> 5;
    const int bcol = (tid & 31) * 4;

    const float* Ap = A  + (size_t)arow * K + acol;
    const float* Bp = Bm + (size_t)brow * Nc + bn + bcol;

    float acc[8][8];
#pragma unroll
    for (int i = 0; i < 8; i++)
#pragma unroll
        for (int j = 0; j < 8; j++) acc[i][j] = 0.0f;

    for (int k0 = 0; k0 < K; k0 += 8) {
        float4 av = *(const float4*)Ap;
        const int sr = tid >> 1;
        As[acol + 0][sr] = av.x;
        As[acol + 1][sr] = av.y;
        As[acol + 2][sr] = av.z;
        As[acol + 3][sr] = av.w;
        *(float4*)(&Bs[brow][bcol]) = *(const float4*)Bp;
        __syncthreads();

#pragma unroll
        for (int k = 0; k < 8; k++) {
            float ra[8], rb[8];
            *(float4*)(ra)     = *(const float4*)(&As[k][ty * 8]);
            *(float4*)(ra + 4) = *(const float4*)(&As[k][ty * 8 + 4]);
            *(float4*)(rb)     = *(const float4*)(&Bs[k][tx * 8]);
            *(float4*)(rb + 4) = *(const float4*)(&Bs[k][tx * 8 + 4]);
#pragma unroll
            for (int i = 0; i < 8; i++)
#pragma unroll
                for (int j = 0; j < 8; j++)
                    acc[i][j] = fmaf(ra[i], rb[j], acc[i][j]);
        }
        __syncthreads();
        Ap += 8;
        Bp += (size_t)8 * Nc;
    }

#pragma unroll
    for (int i = 0; i < 8; i++) {
        const int row = bm + ty * 8 + i;
        if (MGUARD && row >= M) continue;
        const size_t base = (size_t)row * Nc + bn + tx * 8;
        float vals[8];
#pragma unroll
        for (int j = 0; j < 8; j++) {
            float v = acc[i][j];
            if (BIAS) v += bias[bn + tx * 8 + j];
            if (ACT == 1) v = fmaxf(v, 0.0f);
            vals[j] = v;
        }
        *(float4*)(&C[base])     = *(float4*)(vals);
        *(float4*)(&C[base + 4]) = *(float4*)(vals + 4);
    }
}

// ---------------------------------------------------------------------------
// Row gather: dst[m,:] = table[idx[m],:] (D floats per row, float4-wide)
// ---------------------------------------------------------------------------
__global__ void gather_rows_k(const float* __restrict__ table,
                              const int* __restrict__ idx,
                              float* __restrict__ dst, int M)
{
    size_t i = (size_t)blockIdx.x * blockDim.x + threadIdx.x;
    if (i >= (size_t)M * (D / 4)) return;
    int row = (int)(i >> 7);
    int c   = (int)(i & 127);
    ((float4*)dst)[i] = ((const float4*)(table + (size_t)idx[row] * D))[c];
}

// ---------------------------------------------------------------------------
// Weight re-layout: [L,H,D,HD] -> [L, D, H*HD]
// ---------------------------------------------------------------------------
__global__ void transpose_w_k(const float* __restrict__ src, float* __restrict__ dst)
{
    int i = blockIdx.x * blockDim.x + threadIdx.x;
    if (i >= (int)WSZ) return;
    int l   = i / (D * D);
    int rem = i % (D * D);
    int d   = rem / D;
    int c   = rem % D;
    int h   = c / HD;
    int e   = c % HD;
    dst[i] = src[(((size_t)l * H + h) * D + d) * HD + e];
}

// ---------------------------------------------------------------------------
// Attention scores + softmax. One block per b (64 threads, thread = neighbor).
// qtab/ktab hold per-row projections of emb_r; rows gathered by index.
// attnw layout [B][H][N].
// ---------------------------------------------------------------------------
__global__ void attn_scores_k(const float* __restrict__ qtab,
                              const float* __restrict__ ktab,
                              const int* __restrict__ q_idx,
                              const int* __restrict__ nbr_r,
                              const float* __restrict__ masks,
                              float* __restrict__ attnw)
{
    const int b = blockIdx.x;
    const int t = threadIdx.x;   // 0..63

    __shared__ float qs[D];
    __shared__ float tile[64][65];
    __shared__ int   rr[64];
    __shared__ float red[64];

    const int qi = q_idx[b];
    for (int i = t; i < D; i += 64) qs[i] = qtab[(size_t)qi * D + i];
    rr[t] = nbr_r[b * N + t];
    const float neg = 1e31f * (1.0f - masks[b * N + t]);
    __syncthreads();

    for (int h = 0; h < H; h++) {
        for (int i = t; i < 64 * 64; i += 64) {
            int row = i >> 6, col = i & 63;
            tile[row][col] = ktab[(size_t)rr[row] * D + h * HD + col];
        }
        __syncthreads();

        float s = 0.0f;
#pragma unroll 8
        for (int d = 0; d < HD; d++) s = fmaf(qs[h * HD + d], tile[t][d], s);
        s = s * 0.125f - neg;

        red[t] = s; __syncthreads();
        for (int off = 32; off; off >>= 1) {
            if (t < off) red[t] = fmaxf(red[t], red[t + off]);
            __syncthreads();
        }
        const float mx = red[0]; __syncthreads();
        const float ex = expf(s - mx);
        red[t] = ex; __syncthreads();
        for (int off = 32; off; off >>= 1) {
            if (t < off) red[t] += red[t + off];
            __syncthreads();
        }
        attnw[((size_t)b * H + h) * N + t] = ex / red[0];
        __syncthreads();
    }
}

// ---------------------------------------------------------------------------
// vsum[h][b][:] = sum_n attnw[b,h,n] * leaky(hw0[b,:] + etab[nbr_e]+rtab[nbr_r])
// One block per b, 128 threads, 4 columns each, 8 head accumulators.
// ---------------------------------------------------------------------------
__global__ void __launch_bounds__(128) vsum_k(
    const float* __restrict__ hw0, const float* __restrict__ etab,
    const float* __restrict__ rtab, const int* __restrict__ nbr_e,
    const int* __restrict__ nbr_r, const float* __restrict__ attnw,
    float* __restrict__ vsum)
{
    const int b = blockIdx.x;
    const int t = threadIdx.x;   // 0..127

    __shared__ float aw[H * N];
    __shared__ int   ne[64], nr[64];

    if (t < 64) {
        ne[t] = nbr_e[b * N + t];
        nr[t] = nbr_r[b * N + t];
    }
    for (int i = t; i < H * N; i += 128) aw[i] = attnw[(size_t)b * H * N + i];
    __syncthreads();

    const int d0 = t * 4;
    const float4 hv = *(const float4*)(hw0 + (size_t)b * D + d0);

    float acc[H][4];
#pragma unroll
    for (int h = 0; h < H; h++)
#pragma unroll
        for (int j = 0; j < 4; j++) acc[h][j] = 0.0f;

    float4 ev = *(const float4*)(etab + (size_t)ne[0] * D + d0);
    float4 rv = *(const float4*)(rtab + (size_t)nr[0] * D + d0);

    for (int n = 0; n < N; n++) {
        float4 ec = ev, rc = rv;
        if (n + 1 < N) {
            ev = *(const float4*)(etab + (size_t)ne[n + 1] * D + d0);
            rv = *(const float4*)(rtab + (size_t)nr[n + 1] * D + d0);
        }
        float v[4], y;
        y = ec.x + rc.x + hv.x; v[0] = (y > 0.0f) ? y : 0.01f * y;
        y = ec.y + rc.y + hv.y; v[1] = (y > 0.0f) ? y : 0.01f * y;
        y = ec.z + rc.z + hv.z; v[2] = (y > 0.0f) ? y : 0.01f * y;
        y = ec.w + rc.w + hv.w; v[3] = (y > 0.0f) ? y : 0.01f * y;
#pragma unroll
        for (int h = 0; h < H; h++) {
            const float a = aw[h * N + n];
#pragma unroll
            for (int j = 0; j < 4; j++) acc[h][j] = fmaf(a, v[j], acc[h][j]);
        }
    }

#pragma unroll
    for (int h = 0; h < H; h++) {
        float4 o = make_float4(acc[h][0], acc[h][1], acc[h][2], acc[h][3]);
        *(float4*)(vsum + ((size_t)h * B + b) * D + d0) = o;
    }
}

// ---------------------------------------------------------------------------
// Per-head projection: x[b, h*64+e] = vsum[h][b][:] @ w[:, h*64+e] + bias
// grid (B/64, H), 256 threads, 64x64 output tile, 4x4 per thread, BK=8.
// ---------------------------------------------------------------------------
__global__ void __launch_bounds__(256) headgemm_k(
    const float* __restrict__ vsum, const float* __restrict__ w,
    const float* __restrict__ bias, float* __restrict__ x)
{
    const int b0 = blockIdx.x * 64;
    const int h  = blockIdx.y;
    const int tid = threadIdx.x;
    const int tx = tid & 15;
    const int ty = tid >> 4;

    __shared__ float As[8][65];
    __shared__ float Bs[8][64];

    const float* Ab = vsum + ((size_t)h * B + b0) * D;
    const float* Bb = w + h * HD;

    float acc[4][4];
#pragma unroll
    for (int i = 0; i < 4; i++)
#pragma unroll
        for (int j = 0; j < 4; j++) acc[i][j] = 0.0f;

    for (int k0 = 0; k0 < D; k0 += 8) {
        {
            int i = tid;           // 0..255
            int row = i >> 3, k = i & 7;
            As[k][row] = Ab[(size_t)row * D + k0 + k];
            i = tid + 256;
            row = i >> 3; k = i & 7;
            As[k][row] = Ab[(size_t)row * D + k0 + k];
        }
        {
            int i = tid;
            Bs[i >> 6][i & 63] = Bb[(size_t)(k0 + (i >> 6)) * D + (i & 63)];
            i = tid + 256;
            Bs[i >> 6][i & 63] = Bb[(size_t)(k0 + (i >> 6)) * D + (i & 63)];
        }
        __syncthreads();
#pragma unroll
        for (int k = 0; k < 8; k++) {
            float ra[4], rb[4];
#pragma unroll
            for (int i = 0; i < 4; i++) ra[i] = As[k][ty * 4 + i];
#pragma unroll
            for (int j = 0; j < 4; j++) rb[j] = Bs[k][tx * 4 + j];
#pragma unroll
            for (int i = 0; i < 4; i++)
#pragma unroll
                for (int j = 0; j < 4; j++)
                    acc[i][j] = fmaf(ra[i], rb[j], acc[i][j]);
        }
        __syncthreads();
    }

#pragma unroll
    for (int i = 0; i < 4; i++) {
        float4 o;
        o.x = acc[i][0] + bias[h * HD + tx * 4 + 0];
        o.y = acc[i][1] + bias[h * HD + tx * 4 + 1];
        o.z = acc[i][2] + bias[h * HD + tx * 4 + 2];
        o.w = acc[i][3] + bias[h * HD + tx * 4 + 3];
        *(float4*)(x + (size_t)(b0 + ty * 4 + i) * D + h * HD + tx * 4) = o;
    }
}

// ---------------------------------------------------------------------------
// hout = layernorm(hin + xin) * g + beta   (biased var, eps 1e-5)
// ---------------------------------------------------------------------------
__global__ void ln_res_k(const float* __restrict__ hin, const float* __restrict__ xin,
                         const float* __restrict__ g, const float* __restrict__ beta,
                         float* __restrict__ hout)
{
    const int b = blockIdx.x;
    const int t = threadIdx.x;  // 0..127
    float v[4];
    float s = 0.0f, s2 = 0.0f;
#pragma unroll
    for (int i = 0; i < 4; i++) {
        int d = t + i * 128;
        float y = hin[(size_t)b * D + d] + xin[(size_t)b * D + d];
        v[i] = y; s += y; s2 += y * y;
    }
    for (int off = 16; off; off >>= 1) {
        s  += __shfl_down_sync(0xffffffffu, s,  off);
        s2 += __shfl_down_sync(0xffffffffu, s2, off);
    }
    __shared__ float ss[4], ss2[4];
    const int w = t >> 5, lane = t & 31;
    if (lane == 0) { ss[w] = s; ss2[w] = s2; }
    __syncthreads();
    if (t == 0) {
        ss[0]  = ss[0] + ss[1] + ss[2] + ss[3];
        ss2[0] = ss2[0] + ss2[1] + ss2[2] + ss2[3];
    }
    __syncthreads();
    const float mean = ss[0] * (1.0f / D);
    const float var  = ss2[0] * (1.0f / D) - mean * mean;
    const float rstd = rsqrtf(var + 1e-5f);
#pragma unroll
    for (int i = 0; i < 4; i++) {
        int d = t + i * 128;
        hout[(size_t)b * D + d] = (v[i] - mean) * rstd * g[d] + beta[d];
    }
}

} // anonymous namespace

// ---------------------------------------------------------------------------
// Host orchestration (graph-capturable)
// ---------------------------------------------------------------------------
extern "C" void kernel_launch(void* const* d_in, const int* in_sizes, int n_in,
                              void* d_out, int out_size)
{
    const int*   e1_idx = (const int*)  d_in[0];
    const int*   q_idx  = (const int*)  d_in[1];
    const int*   nbr_r  = (const int*)  d_in[2];
    const int*   nbr_e  = (const int*)  d_in[3];
    const float* masks  = (const float*)d_in[4];
    const float* emb_e  = (const float*)d_in[5];
    const float* emb_r  = (const float*)d_in[6];
    const float* msg_W  = (const float*)d_in[7];
    const float* msg_b  = (const float*)d_in[8];
    const float* Wq     = (const float*)d_in[9];
    const float* bq     = (const float*)d_in[10];
    const float* Wk     = (const float*)d_in[11];
    const float* bk     = (const float*)d_in[12];
    const float* Wv     = (const float*)d_in[13];
    const float* bv     = (const float*)d_in[14];
    const float* ffW1   = (const float*)d_in[15];
    const float* ffb1   = (const float*)d_in[16];
    const float* ffW2   = (const float*)d_in[17];
    const float* ffb2   = (const float*)d_in[18];
    const float* ln1g   = (const float*)d_in[19];
    const float* ln1b   = (const float*)d_in[20];
    const float* ln2g   = (const float*)d_in[21];
    const float* ln2b   = (const float*)d_in[22];
    float*       out    = (float*)d_out;

    float* buf = nullptr;
    cudaGetSymbolAddress((void**)&buf, g_buf);

    float* etab = buf + OFF_ETAB;
    float* rtab = buf + OFF_RTAB;
    float* qtab = buf + OFF_QTAB;
    float* ktab = buf + OFF_KTAB;
    float* attw = buf + OFF_ATTN;
    float* vsum = buf + OFF_VSUM;
    float* hb   = buf + OFF_H;
    float* xb   = buf + OFF_X;
    float* hw0  = buf + OFF_HW0;
    float* embq = buf + OFF_EMBQ;
    float* ffm  = buf + OFF_FFM;
    float* wqt  = buf + OFF_WQT;
    float* wkt  = buf + OFF_WKT;
    float* wvt  = buf + OFF_WVT;

    // --- weight re-layout (tiny) ---
    const int TGRID = (int)((WSZ + 255) / 256);
    transpose_w_k<<<TGRID, 256>>>(Wq, wqt);
    transpose_w_k<<<TGRID, 256>>>(Wk, wkt);
    transpose_w_k<<<TGRID, 256>>>(Wv, wvt);

    // --- gathers (only [B,D]-sized; no B*N materialization anywhere) ---
    gather_rows_k<<<(int)(B * (D / 4) / 256), 256>>>(emb_e, e1_idx, hb, B);
    gather_rows_k<<<(int)(B * (D / 4) / 256), 256>>>(emb_r, q_idx, embq, B);

    const dim3 gE (D / 128, (E_ + 127) / 128);  // (4, 782)
    const dim3 gR (D / 128, (R_ + 127) / 128);  // (4, 4)
    const dim3 gSm(D / 128, B / 128);           // (4, 16)
    const dim3 gFF1(FF / 128, B / 128);         // (16, 16)

    // --- layer-invariant tables ---
    // etab = emb_e @ W2 (message e-term for the WHOLE entity table)
    sgemm_k<0, false, true><<<gE, 256>>>(emb_e, msg_W + (size_t)2 * D * D, nullptr, etab, E_, D, D);
    // rtab = emb_r @ W1 (message r-term for the relation table)
    sgemm_k<0, false, true><<<gR, 256>>>(emb_r, msg_W + (size_t)D * D,     nullptr, rtab, R_, D, D);

    // hw0 = h @ W0 + msg_b  (per-entity message term for current h)
    sgemm_k<0, true, false><<<gSm, 256>>>(hb, msg_W, msg_b, hw0, B, D, D);

    for (int l = 0; l < L; l++) {
        // per-relation q/k tables (400 rows each — replaces 131072-row GEMMs)
        sgemm_k<0, true, true><<<gR, 256>>>(emb_r, wqt + (size_t)l * D * D, bq + l * D, qtab, R_, D, D);
        sgemm_k<0, true, true><<<gR, 256>>>(emb_r, wkt + (size_t)l * D * D, bk + l * D, ktab, R_, D, D);

        // attention weights
        attn_scores_k<<<B, 64>>>(qtab, ktab, q_idx, nbr_r, masks, attw);

        // attn-weighted message sum (value computed on the fly, never stored)
        vsum_k<<<B, 128>>>(hw0, etab, rtab, nbr_e, nbr_r, attw, vsum);

        // x = per-head vsum @ Wv + bv
        headgemm_k<<<dim3(B / 64, H), 256>>>(vsum, wvt + (size_t)l * D * D, bv + l * D, xb);

        // h = LN1(h + x)
        ln_res_k<<<B, 128>>>(hb, xb, ln1g + l * D, ln1b + l * D, hb);

        // FF
        sgemm_k<1, true, false><<<gFF1, 256>>>(hb,  ffW1 + (size_t)l * D * FF, ffb1 + l * FF, ffm, B, FF, D);
        sgemm_k<0, true, false><<<gSm,  256>>>(ffm, ffW2 + (size_t)l * FF * D, ffb2 + l * D,  xb,  B, D, FF);

        // h = LN2(h + ff)
        ln_res_k<<<B, 128>>>(hb, xb, ln2g + l * D, ln2b + l * D, hb);

        // message h-term for next layer's value (dead after last layer)
        if (l + 1 < L)
            sgemm_k<0, true, false><<<gSm, 256>>>(hb, msg_W, msg_b, hw0, B, D, D);
    }

    // output = concat(h [B,D], emb_q [B,D])
    cudaMemcpyAsync(out, hb, BD * sizeof(float), cudaMemcpyDeviceToDevice);
    if ((size_t)out_size >= 2 * BD)
        cudaMemcpyAsync(out + BD, embq, BD * sizeof(float), cudaMemcpyDeviceToDevice);
}